// round 1
// baseline (speedup 1.0000x reference)
#include <cuda_runtime.h>

#define VOCABSZ 32000
#define EMBEDSZ 100
#define HIDDENSZ 128
#define BATCHSZ 1024
#define TSTEPS 256

// Scratch (device globals — no allocation APIs allowed)
__device__ float g_P[VOCABSZ * HIDDENSZ];   // projected embeddings + biases, 16.4 MB
__device__ float g_h[BATCHSZ * HIDDENSZ];   // final hidden state
__device__ int   g_x_i64;                   // 1 if x is int64, 0 if int32

// ---------------------------------------------------------------------------
// Packed fp32x2 helpers (Blackwell f32x2 pipe: 2 fp32 FMAs per instruction)
// ---------------------------------------------------------------------------
__device__ __forceinline__ void ffma2(unsigned long long& d,
                                      unsigned long long a,
                                      unsigned long long b) {
    asm("fma.rn.f32x2 %0, %1, %2, %0;" : "+l"(d) : "l"(a), "l"(b));
}
__device__ __forceinline__ float f2sum(unsigned long long v) {
    float lo = __uint_as_float((unsigned int)(v & 0xffffffffull));
    float hi = __uint_as_float((unsigned int)(v >> 32));
    return lo + hi;
}

// ---------------------------------------------------------------------------
// Kernel 0: probe index dtype. If x is int32, an int64-interpretation of the
// buffer packs two indices per word, so the high 32 bits (= the odd-position
// index, uniform in [0,32000)) are nonzero with overwhelming probability
// across 64 samples. Deterministic.
// ---------------------------------------------------------------------------
__global__ void probe_kernel(const void* __restrict__ x) {
    if (threadIdx.x == 0) {
        const long long* p = (const long long*)x;
        int ok = 1;
        #pragma unroll 1
        for (int i = 0; i < 64; i++) {
            long long v = p[i];
            if (v < 0 || v >= VOCABSZ) ok = 0;
        }
        g_x_i64 = ok;
    }
}

// ---------------------------------------------------------------------------
// Kernel 1: P[v][j] = sum_e emb[v][e] * W_ih[j][e] + b_ih[j] + b_hh[j]
// 128 threads (j = tid), W_ih row held in registers (100 floats = 25 u64x2),
// 32 vocab rows per block staged in smem, broadcast reads.
// ---------------------------------------------------------------------------
__global__ __launch_bounds__(128) void proj_kernel(const float* __restrict__ emb,
                                                   const float* __restrict__ W_ih,
                                                   const float* __restrict__ b_ih,
                                                   const float* __restrict__ b_hh) {
    __shared__ ulonglong2 e_sh[32][25];
    const int tid = threadIdx.x;
    const int v0 = blockIdx.x * 32;

    // W_ih row j into registers (row = 400 B, 16B-aligned)
    ulonglong2 w[25];
    const ulonglong2* wr = reinterpret_cast<const ulonglong2*>(W_ih + tid * EMBEDSZ);
    #pragma unroll
    for (int i = 0; i < 25; i++) w[i] = wr[i];

    // stage 32 embedding rows
    for (int idx = tid; idx < 32 * 25; idx += 128) {
        int r = idx / 25, eg = idx % 25;
        e_sh[r][eg] = reinterpret_cast<const ulonglong2*>(
            emb + (long long)(v0 + r) * EMBEDSZ)[eg];
    }
    __syncthreads();

    const float bias = b_ih[tid] + b_hh[tid];

    #pragma unroll 1
    for (int vv = 0; vv < 32; vv += 4) {
        unsigned long long a[4][2] = {};
        #pragma unroll
        for (int eg = 0; eg < 25; eg++) {
            #pragma unroll
            for (int r = 0; r < 4; r++) {
                ulonglong2 e = e_sh[vv + r][eg];
                ffma2(a[r][0], w[eg].x, e.x);
                ffma2(a[r][1], w[eg].y, e.y);
            }
        }
        #pragma unroll
        for (int r = 0; r < 4; r++) {
            g_P[(long long)(v0 + vv + r) * HIDDENSZ + tid] =
                f2sum(a[r][0]) + f2sum(a[r][1]) + bias;
        }
    }
}

// ---------------------------------------------------------------------------
// Kernel 2: persistent RNN scan. One block = 4 batch rows, all 256 steps.
// Block of 128 threads; thread j owns W_hh row j in 128 registers.
// h double-buffered in smem; next-step P rows prefetched during the FMAs.
// Per step per SM (2 blocks resident): 8*128*128 MACs / 128 per cyc = 1024 cyc.
// ---------------------------------------------------------------------------
__global__ __launch_bounds__(128, 2) void rnn_kernel(const void* __restrict__ x,
                                                     const float* __restrict__ W_hh) {
    __shared__ float4 h_sh[2][4][32];     // [buf][row][kgroup of 4 k]
    __shared__ int    xi[4][TSTEPS];

    const int tid = threadIdx.x;
    const int r0 = blockIdx.x * 4;

    // W_hh row j -> registers (512 B row, 16B-aligned)
    ulonglong2 w[32];
    const ulonglong2* wr = reinterpret_cast<const ulonglong2*>(W_hh + tid * HIDDENSZ);
    #pragma unroll
    for (int i = 0; i < 32; i++) w[i] = wr[i];

    // stage this block's token indices
    const int is64 = g_x_i64;
    for (int idx = tid; idx < 4 * TSTEPS; idx += 128) {
        int r = idx >> 8, t = idx & 255;
        long long off = (long long)(r0 + r) * TSTEPS + t;
        int v = is64 ? (int)((const long long*)x)[off]
                     : ((const int*)x)[off];
        xi[r][t] = v;
    }
    // h0 = 0
    #pragma unroll
    for (int r = 0; r < 4; r++) ((float*)&h_sh[0][r][0])[tid] = 0.0f;
    __syncthreads();

    float pcur[4];
    #pragma unroll
    for (int r = 0; r < 4; r++)
        pcur[r] = g_P[(long long)xi[r][0] * HIDDENSZ + tid];

    int buf = 0;
    float hnew[4] = {0.f, 0.f, 0.f, 0.f};

    #pragma unroll 1
    for (int t = 0; t < TSTEPS; t++) {
        // prefetch next step's projected inputs (hidden under the FMAs below)
        float pn[4] = {0.f, 0.f, 0.f, 0.f};
        if (t + 1 < TSTEPS) {
            #pragma unroll
            for (int r = 0; r < 4; r++)
                pn[r] = g_P[(long long)xi[r][t + 1] * HIDDENSZ + tid];
        }

        unsigned long long a[4][2] = {};
        #pragma unroll
        for (int kg = 0; kg < 32; kg++) {
            #pragma unroll
            for (int r = 0; r < 4; r++) {
                ulonglong2 hq =
                    reinterpret_cast<const ulonglong2*>(&h_sh[buf][r][0])[kg];
                ffma2(a[r][0], w[kg].x, hq.x);
                ffma2(a[r][1], w[kg].y, hq.y);
            }
        }

        #pragma unroll
        for (int r = 0; r < 4; r++) {
            float s = f2sum(a[r][0]) + f2sum(a[r][1]);
            hnew[r] = tanhf(pcur[r] + s);
            ((float*)&h_sh[buf ^ 1][r][0])[tid] = hnew[r];
            pcur[r] = pn[r];
        }
        __syncthreads();
        buf ^= 1;
    }

    #pragma unroll
    for (int r = 0; r < 4; r++)
        g_h[(long long)(r0 + r) * HIDDENSZ + tid] = hnew[r];
}

// ---------------------------------------------------------------------------
// Kernel 3: out[b][v] = sum_k h[b][k] * W_fc[v][k] + b_fc[v]
// 64 (b) x 128 (v) tile per block, 256 threads, each thread 4v x 8b outputs.
// W tile staged in smem padded to 33 float4 (conflict-free: lane stride 33%8=1).
// h tile staged unpadded (reads are warp-broadcast). f32x2 accumulators.
// ---------------------------------------------------------------------------
__global__ __launch_bounds__(256) void fc_kernel(const float* __restrict__ W_fc,
                                                 const float* __restrict__ b_fc,
                                                 float* __restrict__ out) {
    extern __shared__ float4 sm4[];
    float4* Wsh = sm4;              // [128][33]
    float4* hsh = sm4 + 128 * 33;   // [64][32]

    const int tid = threadIdx.x;
    const int tv = tid & 31, tb = tid >> 5;
    const int v0 = blockIdx.x * 128;
    const long long b0 = (long long)blockIdx.y * 64;

    for (int idx = tid; idx < 128 * 32; idx += 256) {
        int v = idx >> 5, kg = idx & 31;
        Wsh[v * 33 + kg] = reinterpret_cast<const float4*>(
            W_fc + (long long)(v0 + v) * HIDDENSZ)[kg];
    }
    for (int idx = tid; idx < 64 * 32; idx += 256) {
        int b = idx >> 5, kg = idx & 31;
        hsh[b * 32 + kg] = reinterpret_cast<const float4*>(
            g_h + (b0 + b) * HIDDENSZ)[kg];
    }
    __syncthreads();

    unsigned long long acc[4][8] = {};
    #pragma unroll
    for (int kg = 0; kg < 32; kg++) {
        ulonglong2 hq[8], wq[4];
        #pragma unroll
        for (int n = 0; n < 8; n++)
            hq[n] = *reinterpret_cast<const ulonglong2*>(&hsh[(tb + 8 * n) * 32 + kg]);
        #pragma unroll
        for (int m = 0; m < 4; m++)
            wq[m] = *reinterpret_cast<const ulonglong2*>(&Wsh[(tv + 32 * m) * 33 + kg]);
        #pragma unroll
        for (int m = 0; m < 4; m++) {
            #pragma unroll
            for (int n = 0; n < 8; n++) {
                ffma2(acc[m][n], wq[m].x, hq[n].x);
                ffma2(acc[m][n], wq[m].y, hq[n].y);
            }
        }
    }

    #pragma unroll
    for (int m = 0; m < 4; m++) {
        float bias = b_fc[v0 + tv + 32 * m];
        #pragma unroll
        for (int n = 0; n < 8; n++) {
            out[(b0 + tb + 8 * n) * VOCABSZ + v0 + tv + 32 * m] =
                f2sum(acc[m][n]) + bias;
        }
    }
}

// ---------------------------------------------------------------------------
// inputs (metadata order): x, emb, W_ih, W_hh, b_ih, b_hh, W_fc, b_fc
// ---------------------------------------------------------------------------
extern "C" void kernel_launch(void* const* d_in, const int* in_sizes, int n_in,
                              void* d_out, int out_size) {
    const void*  x    = d_in[0];
    const float* emb  = (const float*)d_in[1];
    const float* W_ih = (const float*)d_in[2];
    const float* W_hh = (const float*)d_in[3];
    const float* b_ih = (const float*)d_in[4];
    const float* b_hh = (const float*)d_in[5];
    const float* W_fc = (const float*)d_in[6];
    const float* b_fc = (const float*)d_in[7];
    float* out = (float*)d_out;

    probe_kernel<<<1, 32>>>(x);
    proj_kernel<<<VOCABSZ / 32, 128>>>(emb, W_ih, b_ih, b_hh);
    rnn_kernel<<<BATCHSZ / 4, 128>>>(x, W_hh);

    const int fc_smem = (128 * 33 + 64 * 32) * (int)sizeof(float4);  // 100352 B
    cudaFuncSetAttribute(fc_kernel, cudaFuncAttributeMaxDynamicSharedMemorySize,
                         fc_smem);
    dim3 fgrid(VOCABSZ / 128, BATCHSZ / 64);  // 250 x 16
    fc_kernel<<<fgrid, 256, fc_smem>>>(W_fc, b_fc, out);
}

// round 3
// speedup vs baseline: 1.3762x; 1.3762x over previous
#include <cuda_runtime.h>

#define VOCABSZ 32000
#define EMBEDSZ 100
#define HIDDENSZ 128
#define BATCHSZ 1024
#define TSTEPS 256

// Scratch (device globals — no allocation APIs allowed)
__device__ float g_P[VOCABSZ * HIDDENSZ];   // projected embeddings + biases, 16.4 MB
__device__ float g_h[BATCHSZ * HIDDENSZ];   // final hidden state
__device__ int   g_x_i64;                   // 1 if x is int64, 0 if int32

// ---------------------------------------------------------------------------
// Packed fp32x2 helpers
// ---------------------------------------------------------------------------
__device__ __forceinline__ void ffma2(unsigned long long& d,
                                      unsigned long long a,
                                      unsigned long long b) {
    asm("fma.rn.f32x2 %0, %1, %2, %0;" : "+l"(d) : "l"(a), "l"(b));
}
__device__ __forceinline__ float f2sum(unsigned long long v) {
    float lo = __uint_as_float((unsigned int)(v & 0xffffffffull));
    float hi = __uint_as_float((unsigned int)(v >> 32));
    return lo + hi;
}

// Branchless fast tanh: 1 - 2/(exp(2x)+1). MUFU.EX2 + MUFU.RCP, ~1e-6 rel err.
__device__ __forceinline__ float fast_tanh(float x) {
    float z = x * 2.885390082f;  // 2*log2(e)
    float e; asm("ex2.approx.f32 %0, %1;" : "=f"(e) : "f"(z));
    float r; asm("rcp.approx.f32 %0, %1;" : "=f"(r) : "f"(e + 1.0f));
    return fmaf(-2.0f, r, 1.0f);
}

// fp32 -> tf32 bit pattern (round-to-nearest-even on 10-bit mantissa)
__device__ __forceinline__ unsigned f2tf32(float f) {
    unsigned r; asm("cvt.rna.tf32.f32 %0, %1;" : "=r"(r) : "f"(f));
    return r;
}

// m16n8k8 tf32 mma, D += A*B
__device__ __forceinline__ void mma_tf32(float* d, const unsigned* a,
                                         const unsigned* b) {
    asm volatile(
        "mma.sync.aligned.m16n8k8.row.col.f32.tf32.tf32.f32 "
        "{%0,%1,%2,%3}, {%4,%5,%6,%7}, {%8,%9}, {%0,%1,%2,%3};"
        : "+f"(d[0]), "+f"(d[1]), "+f"(d[2]), "+f"(d[3])
        : "r"(a[0]), "r"(a[1]), "r"(a[2]), "r"(a[3]), "r"(b[0]), "r"(b[1]));
}

// ---------------------------------------------------------------------------
// Kernel 0: probe index dtype (int64 vs int32), deterministic.
// ---------------------------------------------------------------------------
__global__ void probe_kernel(const void* __restrict__ x) {
    if (threadIdx.x == 0) {
        const long long* p = (const long long*)x;
        int ok = 1;
        #pragma unroll 1
        for (int i = 0; i < 64; i++) {
            long long v = p[i];
            if (v < 0 || v >= VOCABSZ) ok = 0;
        }
        g_x_i64 = ok;
    }
}

// ---------------------------------------------------------------------------
// Kernel 1: P[v][j] = sum_e emb[v][e] * W_ih[j][e] + b_ih[j] + b_hh[j]
// ---------------------------------------------------------------------------
__global__ __launch_bounds__(128) void proj_kernel(const float* __restrict__ emb,
                                                   const float* __restrict__ W_ih,
                                                   const float* __restrict__ b_ih,
                                                   const float* __restrict__ b_hh) {
    __shared__ ulonglong2 e_sh[32][25];
    const int tid = threadIdx.x;
    const int v0 = blockIdx.x * 32;

    ulonglong2 w[25];
    const ulonglong2* wr = reinterpret_cast<const ulonglong2*>(W_ih + tid * EMBEDSZ);
    #pragma unroll
    for (int i = 0; i < 25; i++) w[i] = wr[i];

    for (int idx = tid; idx < 32 * 25; idx += 128) {
        int r = idx / 25, eg = idx % 25;
        e_sh[r][eg] = reinterpret_cast<const ulonglong2*>(
            emb + (long long)(v0 + r) * EMBEDSZ)[eg];
    }
    __syncthreads();

    const float bias = b_ih[tid] + b_hh[tid];

    #pragma unroll 1
    for (int vv = 0; vv < 32; vv += 4) {
        unsigned long long a[4][2] = {};
        #pragma unroll
        for (int eg = 0; eg < 25; eg++) {
            #pragma unroll
            for (int r = 0; r < 4; r++) {
                ulonglong2 e = e_sh[vv + r][eg];
                ffma2(a[r][0], w[eg].x, e.x);
                ffma2(a[r][1], w[eg].y, e.y);
            }
        }
        #pragma unroll
        for (int r = 0; r < 4; r++) {
            g_P[(long long)(v0 + vv + r) * HIDDENSZ + tid] =
                f2sum(a[r][0]) + f2sum(a[r][1]) + bias;
        }
    }
}

// ---------------------------------------------------------------------------
// Kernel 2: persistent RNN scan. One block = 4 batch rows, all 256 steps.
// Thread j holds W_hh row j in 128 registers; h double-buffered in smem.
// ---------------------------------------------------------------------------
__global__ __launch_bounds__(128, 2) void rnn_kernel(const void* __restrict__ x,
                                                     const float* __restrict__ W_hh) {
    __shared__ float4 h_sh[2][4][32];
    __shared__ int    xi[4][TSTEPS];

    const int tid = threadIdx.x;
    const int r0 = blockIdx.x * 4;

    ulonglong2 w[32];
    const ulonglong2* wr = reinterpret_cast<const ulonglong2*>(W_hh + tid * HIDDENSZ);
    #pragma unroll
    for (int i = 0; i < 32; i++) w[i] = wr[i];

    const int is64 = g_x_i64;
    for (int idx = tid; idx < 4 * TSTEPS; idx += 128) {
        int r = idx >> 8, t = idx & 255;
        long long off = (long long)(r0 + r) * TSTEPS + t;
        int v = is64 ? (int)((const long long*)x)[off]
                     : ((const int*)x)[off];
        xi[r][t] = v;
    }
    #pragma unroll
    for (int r = 0; r < 4; r++) ((float*)&h_sh[0][r][0])[tid] = 0.0f;
    __syncthreads();

    float pcur[4];
    #pragma unroll
    for (int r = 0; r < 4; r++)
        pcur[r] = g_P[(long long)xi[r][0] * HIDDENSZ + tid];

    int buf = 0;
    float hnew[4] = {0.f, 0.f, 0.f, 0.f};

    #pragma unroll 1
    for (int t = 0; t < TSTEPS; t++) {
        float pn[4] = {0.f, 0.f, 0.f, 0.f};
        if (t + 1 < TSTEPS) {
            #pragma unroll
            for (int r = 0; r < 4; r++)
                pn[r] = g_P[(long long)xi[r][t + 1] * HIDDENSZ + tid];
        }

        unsigned long long a[4][2] = {};
        #pragma unroll
        for (int kg = 0; kg < 32; kg++) {
            #pragma unroll
            for (int r = 0; r < 4; r++) {
                ulonglong2 hq =
                    reinterpret_cast<const ulonglong2*>(&h_sh[buf][r][0])[kg];
                ffma2(a[r][0], w[kg].x, hq.x);
                ffma2(a[r][1], w[kg].y, hq.y);
            }
        }

        #pragma unroll
        for (int r = 0; r < 4; r++) {
            float s = f2sum(a[r][0]) + f2sum(a[r][1]);
            hnew[r] = fast_tanh(pcur[r] + s);
            ((float*)&h_sh[buf ^ 1][r][0])[tid] = hnew[r];
            pcur[r] = pn[r];
        }
        __syncthreads();
        buf ^= 1;
    }

    #pragma unroll
    for (int r = 0; r < 4; r++)
        g_h[(long long)(r0 + r) * HIDDENSZ + tid] = hnew[r];
}

// ---------------------------------------------------------------------------
// Kernel 3: FC head via tf32 tensor cores.
// out[b][v] = sum_k h[b][k]*W_fc[v][k] + b_fc[v]
// Block tile: 128b x 128v, 256 threads (8 warps = 2 m-groups x 4 n-groups,
// each warp 4 m16-tiles x 4 n8-tiles x 16 k-steps = 256 mma).
// Operands staged in smem as tf32 bit patterns, stride 132 words so every
// fragment load hits 32 distinct banks.
// ---------------------------------------------------------------------------
#define FCS 132  // smem row stride in words (132 % 32 == 4 -> conflict-free)

__global__ __launch_bounds__(256) void fc_kernel(const float* __restrict__ W_fc,
                                                 const float* __restrict__ b_fc,
                                                 float* __restrict__ out) {
    extern __shared__ unsigned sm_u[];
    unsigned* Ws = sm_u;               // [128][FCS] tf32 of W_fc tile
    unsigned* Hs = sm_u + 128 * FCS;   // [128][FCS] tf32 of h tile

    const int tid  = threadIdx.x;
    const int lane = tid & 31;
    const int w    = tid >> 5;
    const int g    = lane >> 2;
    const int t4   = lane & 3;
    const int v0   = blockIdx.x * 128;
    const int b0   = blockIdx.y * 128;
    const int mw   = w >> 2;   // 0..1  (64 b-rows each)
    const int nw   = w & 3;    // 0..3  (32 v-cols each)

    // Stage + convert both tiles (uint4 stores, conflict-free)
    for (int idx = tid; idx < 128 * 32; idx += 256) {
        int r = idx >> 5, c4 = idx & 31;
        float4 wv = reinterpret_cast<const float4*>(
            W_fc + (long long)(v0 + r) * HIDDENSZ)[c4];
        uint4 wt = {f2tf32(wv.x), f2tf32(wv.y), f2tf32(wv.z), f2tf32(wv.w)};
        *reinterpret_cast<uint4*>(Ws + r * FCS + c4 * 4) = wt;

        float4 hv = reinterpret_cast<const float4*>(
            g_h + (long long)(b0 + r) * HIDDENSZ)[c4];
        uint4 ht = {f2tf32(hv.x), f2tf32(hv.y), f2tf32(hv.z), f2tf32(hv.w)};
        *reinterpret_cast<uint4*>(Hs + r * FCS + c4 * 4) = ht;
    }
    __syncthreads();

    float acc[4][4][4] = {};

    #pragma unroll
    for (int k = 0; k < 16; k++) {
        const int kc = k * 8 + t4;
        unsigned a[4][4], b[4][2];
        #pragma unroll
        for (int mi = 0; mi < 4; mi++) {
            const unsigned* base = Hs + (mw * 64 + mi * 16 + g) * FCS;
            a[mi][0] = base[kc];
            a[mi][1] = base[8 * FCS + kc];
            a[mi][2] = base[kc + 4];
            a[mi][3] = base[8 * FCS + kc + 4];
        }
        #pragma unroll
        for (int ni = 0; ni < 4; ni++) {
            const unsigned* base = Ws + (nw * 32 + ni * 8 + g) * FCS;
            b[ni][0] = base[kc];
            b[ni][1] = base[kc + 4];
        }
        #pragma unroll
        for (int mi = 0; mi < 4; mi++)
            #pragma unroll
            for (int ni = 0; ni < 4; ni++)
                mma_tf32(acc[mi][ni], a[mi], b[ni]);
    }

    // Epilogue: bias + float2 stores
    #pragma unroll
    for (int ni = 0; ni < 4; ni++) {
        int v = v0 + nw * 32 + ni * 8 + 2 * t4;
        float2 bb = *reinterpret_cast<const float2*>(b_fc + v);
        #pragma unroll
        for (int mi = 0; mi < 4; mi++) {
            int br = b0 + mw * 64 + mi * 16 + g;
            float2 r0 = {acc[mi][ni][0] + bb.x, acc[mi][ni][1] + bb.y};
            float2 r1 = {acc[mi][ni][2] + bb.x, acc[mi][ni][3] + bb.y};
            *reinterpret_cast<float2*>(out + (long long)br * VOCABSZ + v) = r0;
            *reinterpret_cast<float2*>(out + (long long)(br + 8) * VOCABSZ + v) = r1;
        }
    }
}

// ---------------------------------------------------------------------------
// inputs (metadata order): x, emb, W_ih, W_hh, b_ih, b_hh, W_fc, b_fc
// ---------------------------------------------------------------------------
extern "C" void kernel_launch(void* const* d_in, const int* in_sizes, int n_in,
                              void* d_out, int out_size) {
    const void*  x    = d_in[0];
    const float* emb  = (const float*)d_in[1];
    const float* W_ih = (const float*)d_in[2];
    const float* W_hh = (const float*)d_in[3];
    const float* b_ih = (const float*)d_in[4];
    const float* b_hh = (const float*)d_in[5];
    const float* W_fc = (const float*)d_in[6];
    const float* b_fc = (const float*)d_in[7];
    float* out = (float*)d_out;

    probe_kernel<<<1, 32>>>(x);
    proj_kernel<<<VOCABSZ / 32, 128>>>(emb, W_ih, b_ih, b_hh);
    rnn_kernel<<<BATCHSZ / 4, 128>>>(x, W_hh);

    const int fc_smem = 2 * 128 * FCS * (int)sizeof(unsigned);  // 135168 B
    cudaFuncSetAttribute(fc_kernel, cudaFuncAttributeMaxDynamicSharedMemorySize,
                         fc_smem);
    dim3 fgrid(VOCABSZ / 128, BATCHSZ / 128);  // 250 x 8
    fc_kernel<<<fgrid, 256, fc_smem>>>(W_fc, b_fc, out);
}

// round 4
// speedup vs baseline: 1.3792x; 1.0021x over previous
#include <cuda_runtime.h>

#define VOCABSZ 32000
#define EMBEDSZ 100
#define HIDDENSZ 128
#define BATCHSZ 1024
#define TSTEPS 256

// Scratch (device globals — no allocation APIs allowed)
__device__ float g_P[VOCABSZ * HIDDENSZ];   // projected embeddings + biases, 16.4 MB
__device__ float g_h[BATCHSZ * HIDDENSZ];   // final hidden state
__device__ int   g_x_i64;                   // 1 if x is int64, 0 if int32

// ---------------------------------------------------------------------------
// Packed fp32x2 helpers
// ---------------------------------------------------------------------------
__device__ __forceinline__ void ffma2(unsigned long long& d,
                                      unsigned long long a,
                                      unsigned long long b) {
    asm("fma.rn.f32x2 %0, %1, %2, %0;" : "+l"(d) : "l"(a), "l"(b));
}
__device__ __forceinline__ float f2sum(unsigned long long v) {
    float lo = __uint_as_float((unsigned int)(v & 0xffffffffull));
    float hi = __uint_as_float((unsigned int)(v >> 32));
    return lo + hi;
}

// Branchless fast tanh: 1 - 2/(exp(2x)+1). MUFU.EX2 + MUFU.RCP, ~1e-6 rel err.
__device__ __forceinline__ float fast_tanh(float x) {
    float z = x * 2.885390082f;  // 2*log2(e)
    float e; asm("ex2.approx.f32 %0, %1;" : "=f"(e) : "f"(z));
    float r; asm("rcp.approx.f32 %0, %1;" : "=f"(r) : "f"(e + 1.0f));
    return fmaf(-2.0f, r, 1.0f);
}

// fp32 -> tf32 bit pattern (round-to-nearest-even on 10-bit mantissa)
__device__ __forceinline__ unsigned f2tf32(float f) {
    unsigned r; asm("cvt.rna.tf32.f32 %0, %1;" : "=r"(r) : "f"(f));
    return r;
}

// m16n8k8 tf32 mma, D += A*B
__device__ __forceinline__ void mma_tf32(float* d, const unsigned* a,
                                         const unsigned* b) {
    asm volatile(
        "mma.sync.aligned.m16n8k8.row.col.f32.tf32.tf32.f32 "
        "{%0,%1,%2,%3}, {%4,%5,%6,%7}, {%8,%9}, {%0,%1,%2,%3};"
        : "+f"(d[0]), "+f"(d[1]), "+f"(d[2]), "+f"(d[3])
        : "r"(a[0]), "r"(a[1]), "r"(a[2]), "r"(a[3]), "r"(b[0]), "r"(b[1]));
}

// ---------------------------------------------------------------------------
// Kernel 0: probe index dtype (int64 vs int32), deterministic.
// ---------------------------------------------------------------------------
__global__ void probe_kernel(const void* __restrict__ x) {
    if (threadIdx.x == 0) {
        const long long* p = (const long long*)x;
        int ok = 1;
        #pragma unroll 1
        for (int i = 0; i < 64; i++) {
            long long v = p[i];
            if (v < 0 || v >= VOCABSZ) ok = 0;
        }
        g_x_i64 = ok;
    }
}

// ---------------------------------------------------------------------------
// Kernel 1: P[v][j] = sum_e emb[v][e] * W_ih[j][e] + b_ih[j] + b_hh[j]
// ---------------------------------------------------------------------------
__global__ __launch_bounds__(128) void proj_kernel(const float* __restrict__ emb,
                                                   const float* __restrict__ W_ih,
                                                   const float* __restrict__ b_ih,
                                                   const float* __restrict__ b_hh) {
    __shared__ ulonglong2 e_sh[32][25];
    const int tid = threadIdx.x;
    const int v0 = blockIdx.x * 32;

    ulonglong2 w[25];
    const ulonglong2* wr = reinterpret_cast<const ulonglong2*>(W_ih + tid * EMBEDSZ);
    #pragma unroll
    for (int i = 0; i < 25; i++) w[i] = wr[i];

    for (int idx = tid; idx < 32 * 25; idx += 128) {
        int r = idx / 25, eg = idx % 25;
        e_sh[r][eg] = reinterpret_cast<const ulonglong2*>(
            emb + (long long)(v0 + r) * EMBEDSZ)[eg];
    }
    __syncthreads();

    const float bias = b_ih[tid] + b_hh[tid];

    #pragma unroll 1
    for (int vv = 0; vv < 32; vv += 4) {
        unsigned long long a[4][2] = {};
        #pragma unroll
        for (int eg = 0; eg < 25; eg++) {
            #pragma unroll
            for (int r = 0; r < 4; r++) {
                ulonglong2 e = e_sh[vv + r][eg];
                ffma2(a[r][0], w[eg].x, e.x);
                ffma2(a[r][1], w[eg].y, e.y);
            }
        }
        #pragma unroll
        for (int r = 0; r < 4; r++) {
            g_P[(long long)(v0 + vv + r) * HIDDENSZ + tid] =
                f2sum(a[r][0]) + f2sum(a[r][1]) + bias;
        }
    }
}

// ---------------------------------------------------------------------------
// Kernel 2: persistent RNN scan. One block = 4 batch rows, all 256 steps.
// Thread j holds W_hh row j in 128 registers; h double-buffered in smem.
// ---------------------------------------------------------------------------
__global__ __launch_bounds__(128, 2) void rnn_kernel(const void* __restrict__ x,
                                                     const float* __restrict__ W_hh) {
    __shared__ float4 h_sh[2][4][32];
    __shared__ int    xi[4][TSTEPS];

    const int tid = threadIdx.x;
    const int r0 = blockIdx.x * 4;

    ulonglong2 w[32];
    const ulonglong2* wr = reinterpret_cast<const ulonglong2*>(W_hh + tid * HIDDENSZ);
    #pragma unroll
    for (int i = 0; i < 32; i++) w[i] = wr[i];

    const int is64 = g_x_i64;
    for (int idx = tid; idx < 4 * TSTEPS; idx += 128) {
        int r = idx >> 8, t = idx & 255;
        long long off = (long long)(r0 + r) * TSTEPS + t;
        int v = is64 ? (int)((const long long*)x)[off]
                     : ((const int*)x)[off];
        xi[r][t] = v;
    }
    #pragma unroll
    for (int r = 0; r < 4; r++) ((float*)&h_sh[0][r][0])[tid] = 0.0f;
    __syncthreads();

    float pcur[4];
    #pragma unroll
    for (int r = 0; r < 4; r++)
        pcur[r] = g_P[(long long)xi[r][0] * HIDDENSZ + tid];

    int buf = 0;
    float hnew[4] = {0.f, 0.f, 0.f, 0.f};

    #pragma unroll 1
    for (int t = 0; t < TSTEPS; t++) {
        float pn[4] = {0.f, 0.f, 0.f, 0.f};
        if (t + 1 < TSTEPS) {
            #pragma unroll
            for (int r = 0; r < 4; r++)
                pn[r] = g_P[(long long)xi[r][t + 1] * HIDDENSZ + tid];
        }

        unsigned long long a[4][2] = {};
        #pragma unroll
        for (int kg = 0; kg < 32; kg++) {
            #pragma unroll
            for (int r = 0; r < 4; r++) {
                ulonglong2 hq =
                    reinterpret_cast<const ulonglong2*>(&h_sh[buf][r][0])[kg];
                ffma2(a[r][0], w[kg].x, hq.x);
                ffma2(a[r][1], w[kg].y, hq.y);
            }
        }

        #pragma unroll
        for (int r = 0; r < 4; r++) {
            float s = f2sum(a[r][0]) + f2sum(a[r][1]);
            hnew[r] = fast_tanh(pcur[r] + s);
            ((float*)&h_sh[buf ^ 1][r][0])[tid] = hnew[r];
            pcur[r] = pn[r];
        }
        __syncthreads();
        buf ^= 1;
    }

    #pragma unroll
    for (int r = 0; r < 4; r++)
        g_h[(long long)(r0 + r) * HIDDENSZ + tid] = hnew[r];
}

// ---------------------------------------------------------------------------
// Kernel 3: FC head via tf32 tensor cores.
// out[b][v] = sum_k h[b][k]*W_fc[v][k] + b_fc[v]
// Block tile: 128b x 128v, 256 threads (8 warps = 2 m-groups x 4 n-groups,
// each warp 4 m16-tiles x 4 n8-tiles x 16 k-steps = 256 mma).
// Operands staged in smem as tf32 bit patterns, stride 132 words so every
// fragment load hits 32 distinct banks.
// ---------------------------------------------------------------------------
#define FCS 132  // smem row stride in words (132 % 32 == 4 -> conflict-free)

__global__ __launch_bounds__(256) void fc_kernel(const float* __restrict__ W_fc,
                                                 const float* __restrict__ b_fc,
                                                 float* __restrict__ out) {
    extern __shared__ unsigned sm_u[];
    unsigned* Ws = sm_u;               // [128][FCS] tf32 of W_fc tile
    unsigned* Hs = sm_u + 128 * FCS;   // [128][FCS] tf32 of h tile

    const int tid  = threadIdx.x;
    const int lane = tid & 31;
    const int w    = tid >> 5;
    const int g    = lane >> 2;
    const int t4   = lane & 3;
    const int v0   = blockIdx.x * 128;
    const int b0   = blockIdx.y * 128;
    const int mw   = w >> 2;   // 0..1  (64 b-rows each)
    const int nw   = w & 3;    // 0..3  (32 v-cols each)

    // Stage + convert both tiles (uint4 stores, conflict-free)
    for (int idx = tid; idx < 128 * 32; idx += 256) {
        int r = idx >> 5, c4 = idx & 31;
        float4 wv = reinterpret_cast<const float4*>(
            W_fc + (long long)(v0 + r) * HIDDENSZ)[c4];
        uint4 wt = {f2tf32(wv.x), f2tf32(wv.y), f2tf32(wv.z), f2tf32(wv.w)};
        *reinterpret_cast<uint4*>(Ws + r * FCS + c4 * 4) = wt;

        float4 hv = reinterpret_cast<const float4*>(
            g_h + (long long)(b0 + r) * HIDDENSZ)[c4];
        uint4 ht = {f2tf32(hv.x), f2tf32(hv.y), f2tf32(hv.z), f2tf32(hv.w)};
        *reinterpret_cast<uint4*>(Hs + r * FCS + c4 * 4) = ht;
    }
    __syncthreads();

    float acc[4][4][4] = {};

    #pragma unroll
    for (int k = 0; k < 16; k++) {
        const int kc = k * 8 + t4;
        unsigned a[4][4], b[4][2];
        #pragma unroll
        for (int mi = 0; mi < 4; mi++) {
            const unsigned* base = Hs + (mw * 64 + mi * 16 + g) * FCS;
            a[mi][0] = base[kc];
            a[mi][1] = base[8 * FCS + kc];
            a[mi][2] = base[kc + 4];
            a[mi][3] = base[8 * FCS + kc + 4];
        }
        #pragma unroll
        for (int ni = 0; ni < 4; ni++) {
            const unsigned* base = Ws + (nw * 32 + ni * 8 + g) * FCS;
            b[ni][0] = base[kc];
            b[ni][1] = base[kc + 4];
        }
        #pragma unroll
        for (int mi = 0; mi < 4; mi++)
            #pragma unroll
            for (int ni = 0; ni < 4; ni++)
                mma_tf32(acc[mi][ni], a[mi], b[ni]);
    }

    // Epilogue: bias + float2 stores
    #pragma unroll
    for (int ni = 0; ni < 4; ni++) {
        int v = v0 + nw * 32 + ni * 8 + 2 * t4;
        float2 bb = *reinterpret_cast<const float2*>(b_fc + v);
        #pragma unroll
        for (int mi = 0; mi < 4; mi++) {
            int br = b0 + mw * 64 + mi * 16 + g;
            float2 r0 = {acc[mi][ni][0] + bb.x, acc[mi][ni][1] + bb.y};
            float2 r1 = {acc[mi][ni][2] + bb.x, acc[mi][ni][3] + bb.y};
            *reinterpret_cast<float2*>(out + (long long)br * VOCABSZ + v) = r0;
            *reinterpret_cast<float2*>(out + (long long)(br + 8) * VOCABSZ + v) = r1;
        }
    }
}

// ---------------------------------------------------------------------------
// inputs (metadata order): x, emb, W_ih, W_hh, b_ih, b_hh, W_fc, b_fc
// ---------------------------------------------------------------------------
extern "C" void kernel_launch(void* const* d_in, const int* in_sizes, int n_in,
                              void* d_out, int out_size) {
    const void*  x    = d_in[0];
    const float* emb  = (const float*)d_in[1];
    const float* W_ih = (const float*)d_in[2];
    const float* W_hh = (const float*)d_in[3];
    const float* b_ih = (const float*)d_in[4];
    const float* b_hh = (const float*)d_in[5];
    const float* W_fc = (const float*)d_in[6];
    const float* b_fc = (const float*)d_in[7];
    float* out = (float*)d_out;

    probe_kernel<<<1, 32>>>(x);
    proj_kernel<<<VOCABSZ / 32, 128>>>(emb, W_ih, b_ih, b_hh);
    rnn_kernel<<<BATCHSZ / 4, 128>>>(x, W_hh);

    const int fc_smem = 2 * 128 * FCS * (int)sizeof(unsigned);  // 135168 B
    cudaFuncSetAttribute(fc_kernel, cudaFuncAttributeMaxDynamicSharedMemorySize,
                         fc_smem);
    dim3 fgrid(VOCABSZ / 128, BATCHSZ / 128);  // 250 x 8
    fc_kernel<<<fgrid, 256, fc_smem>>>(W_fc, b_fc, out);
}

// round 5
// speedup vs baseline: 1.4830x; 1.0753x over previous
#include <cuda_runtime.h>

#define VOCABSZ 32000
#define EMBEDSZ 100
#define HIDDENSZ 128
#define BATCHSZ 1024
#define TSTEPS 256

// Scratch (device globals — no allocation APIs allowed)
__device__ float g_P[VOCABSZ * HIDDENSZ];   // projected embeddings + biases, 16.4 MB
__device__ float g_h[BATCHSZ * HIDDENSZ];   // final hidden state
__device__ int   g_x_i64;                   // 1 if x is int64, 0 if int32

// ---------------------------------------------------------------------------
// Helpers
// ---------------------------------------------------------------------------
__device__ __forceinline__ void ffma2(unsigned long long& d,
                                      unsigned long long a,
                                      unsigned long long b) {
    asm("fma.rn.f32x2 %0, %1, %2, %0;" : "+l"(d) : "l"(a), "l"(b));
}
__device__ __forceinline__ float f2sum(unsigned long long v) {
    float lo = __uint_as_float((unsigned int)(v & 0xffffffffull));
    float hi = __uint_as_float((unsigned int)(v >> 32));
    return lo + hi;
}

// Branchless fast tanh: 1 - 2/(exp(2x)+1). MUFU.EX2 + MUFU.RCP, ~1e-6 rel err.
__device__ __forceinline__ float fast_tanh(float x) {
    float z = x * 2.885390082f;  // 2*log2(e)
    float e; asm("ex2.approx.f32 %0, %1;" : "=f"(e) : "f"(z));
    float r; asm("rcp.approx.f32 %0, %1;" : "=f"(r) : "f"(e + 1.0f));
    return fmaf(-2.0f, r, 1.0f);
}

// fp32 -> tf32 bit pattern (round-to-nearest on 10-bit mantissa)
__device__ __forceinline__ unsigned f2tf32(float f) {
    unsigned r; asm("cvt.rna.tf32.f32 %0, %1;" : "=r"(r) : "f"(f));
    return r;
}

// m16n8k8 tf32 mma, D += A*B
__device__ __forceinline__ void mma_tf32(float* d, const unsigned* a,
                                         const unsigned* b) {
    asm volatile(
        "mma.sync.aligned.m16n8k8.row.col.f32.tf32.tf32.f32 "
        "{%0,%1,%2,%3}, {%4,%5,%6,%7}, {%8,%9}, {%0,%1,%2,%3};"
        : "+f"(d[0]), "+f"(d[1]), "+f"(d[2]), "+f"(d[3])
        : "r"(a[0]), "r"(a[1]), "r"(a[2]), "r"(a[3]), "r"(b[0]), "r"(b[1]));
}

// ---------------------------------------------------------------------------
// Kernel 0: probe index dtype (int64 vs int32), deterministic.
// ---------------------------------------------------------------------------
__global__ void probe_kernel(const void* __restrict__ x) {
    if (threadIdx.x == 0) {
        const long long* p = (const long long*)x;
        int ok = 1;
        #pragma unroll 1
        for (int i = 0; i < 64; i++) {
            long long v = p[i];
            if (v < 0 || v >= VOCABSZ) ok = 0;
        }
        g_x_i64 = ok;
    }
}

// ---------------------------------------------------------------------------
// Kernel 1: P[v][j] = sum_e emb[v][e] * W_ih[j][e] + b_ih[j] + b_hh[j]
// ---------------------------------------------------------------------------
__global__ __launch_bounds__(128) void proj_kernel(const float* __restrict__ emb,
                                                   const float* __restrict__ W_ih,
                                                   const float* __restrict__ b_ih,
                                                   const float* __restrict__ b_hh) {
    __shared__ ulonglong2 e_sh[32][25];
    const int tid = threadIdx.x;
    const int v0 = blockIdx.x * 32;

    ulonglong2 w[25];
    const ulonglong2* wr = reinterpret_cast<const ulonglong2*>(W_ih + tid * EMBEDSZ);
    #pragma unroll
    for (int i = 0; i < 25; i++) w[i] = wr[i];

    for (int idx = tid; idx < 32 * 25; idx += 128) {
        int r = idx / 25, eg = idx % 25;
        e_sh[r][eg] = reinterpret_cast<const ulonglong2*>(
            emb + (long long)(v0 + r) * EMBEDSZ)[eg];
    }
    __syncthreads();

    const float bias = b_ih[tid] + b_hh[tid];

    #pragma unroll 1
    for (int vv = 0; vv < 32; vv += 4) {
        unsigned long long a[4][2] = {};
        #pragma unroll
        for (int eg = 0; eg < 25; eg++) {
            #pragma unroll
            for (int r = 0; r < 4; r++) {
                ulonglong2 e = e_sh[vv + r][eg];
                ffma2(a[r][0], w[eg].x, e.x);
                ffma2(a[r][1], w[eg].y, e.y);
            }
        }
        #pragma unroll
        for (int r = 0; r < 4; r++) {
            g_P[(long long)(v0 + vv + r) * HIDDENSZ + tid] =
                f2sum(a[r][0]) + f2sum(a[r][1]) + bias;
        }
    }
}

// ---------------------------------------------------------------------------
// Kernel 2: tensor-core RNN scan (3x-tf32 split, full fp32-class accuracy).
// Block = 8 batch rows, 8 warps (256 threads). Warp w owns h-columns
// [w*16, w*16+16) = 2 n8-tiles. W_hh column-fragments (hi+lo) live in 128
// registers per thread. h kept in smem as split (tf32_hi, tf32_lo), double
// buffered; one __syncthreads per step. A-fragment uses rows g (rows 8..15
// of the m16 tile are zero => a1=a3=0, halving smem traffic).
// D += A_hi*B_hi + A_hi*B_lo + A_lo*B_hi  (error ~2^-21 per step).
// ---------------------------------------------------------------------------
#define RS 132   // smem row stride (words): (4g + t4) mod 32 distinct => conflict-free

__global__ __launch_bounds__(256, 1) void rnn_kernel(const void* __restrict__ x,
                                                     const float* __restrict__ W_hh) {
    __shared__ unsigned Hhi[2][8 * RS];
    __shared__ unsigned Hlo[2][8 * RS];
    __shared__ int      xi[8][TSTEPS];

    const int tid  = threadIdx.x;
    const int lane = tid & 31;
    const int w    = tid >> 5;
    const int g    = lane >> 2;      // 0..7  (row within 8, and col-row group)
    const int t4   = lane & 3;
    const int c0   = w * 16;         // this warp's first output column
    const int r0   = blockIdx.x * 8; // first batch row of this block

    // --- stationary B fragments: W_hh[j][k], j = out col, split hi/lo ---
    unsigned bh[2][16][2], bl[2][16][2];
    #pragma unroll
    for (int ni = 0; ni < 2; ni++) {
        #pragma unroll
        for (int kt = 0; kt < 16; kt++) {
            int j = c0 + ni * 8 + g;
            int k = kt * 8 + t4;
            float w0 = __ldg(W_hh + j * HIDDENSZ + k);
            float w1 = __ldg(W_hh + j * HIDDENSZ + k + 4);
            unsigned h0 = f2tf32(w0), h1 = f2tf32(w1);
            bh[ni][kt][0] = h0;
            bh[ni][kt][1] = h1;
            bl[ni][kt][0] = f2tf32(w0 - __uint_as_float(h0));
            bl[ni][kt][1] = f2tf32(w1 - __uint_as_float(h1));
        }
    }

    // --- stage token indices, zero h buffer 0 ---
    const int is64 = g_x_i64;
    for (int idx = tid; idx < 8 * TSTEPS; idx += 256) {
        int r = idx >> 8, t = idx & 255;
        long long off = (long long)(r0 + r) * TSTEPS + t;
        int v = is64 ? (int)((const long long*)x)[off]
                     : ((const int*)x)[off];
        xi[r][t] = v;
    }
    for (int idx = tid; idx < 8 * RS; idx += 256) {
        Hhi[0][idx] = 0u;
        Hlo[0][idx] = 0u;
    }
    __syncthreads();

    // --- pcur: this thread's P entries (row g; cols c0+ni*8+2t4, +1) ---
    float2 pcur[2];
    #pragma unroll
    for (int ni = 0; ni < 2; ni++)
        pcur[ni] = *reinterpret_cast<const float2*>(
            g_P + (long long)xi[g][0] * HIDDENSZ + c0 + ni * 8 + 2 * t4);

    int buf = 0;

    #pragma unroll 1
    for (int t = 0; t < TSTEPS; t++) {
        // prefetch next step's P
        float2 pn[2] = {{0.f, 0.f}, {0.f, 0.f}};
        if (t + 1 < TSTEPS) {
            int v = xi[g][t + 1];
            #pragma unroll
            for (int ni = 0; ni < 2; ni++)
                pn[ni] = *reinterpret_cast<const float2*>(
                    g_P + (long long)v * HIDDENSZ + c0 + ni * 8 + 2 * t4);
        }

        float acc[2][4] = {};
        const unsigned* Hh = Hhi[buf];
        const unsigned* Hl = Hlo[buf];

        #pragma unroll
        for (int kt = 0; kt < 16; kt++) {
            const int kc = kt * 8 + t4;
            unsigned ah[4], al[4];
            ah[0] = Hh[g * RS + kc];  ah[1] = 0u;
            ah[2] = Hh[g * RS + kc + 4]; ah[3] = 0u;
            al[0] = Hl[g * RS + kc];  al[1] = 0u;
            al[2] = Hl[g * RS + kc + 4]; al[3] = 0u;
            #pragma unroll
            for (int ni = 0; ni < 2; ni++) {
                mma_tf32(acc[ni], ah, bh[ni][kt]);
                mma_tf32(acc[ni], ah, bl[ni][kt]);
                mma_tf32(acc[ni], al, bh[ni][kt]);
            }
        }

        // epilogue: preact -> tanh -> split -> store to other buffer
        unsigned* dHh = Hhi[buf ^ 1];
        unsigned* dHl = Hlo[buf ^ 1];
        #pragma unroll
        for (int ni = 0; ni < 2; ni++) {
            float v0 = fast_tanh(acc[ni][0] + pcur[ni].x);
            float v1 = fast_tanh(acc[ni][1] + pcur[ni].y);
            unsigned u0 = f2tf32(v0), u1 = f2tf32(v1);
            unsigned l0 = f2tf32(v0 - __uint_as_float(u0));
            unsigned l1 = f2tf32(v1 - __uint_as_float(u1));
            int c = c0 + ni * 8 + 2 * t4;
            *reinterpret_cast<uint2*>(&dHh[g * RS + c]) = make_uint2(u0, u1);
            *reinterpret_cast<uint2*>(&dHl[g * RS + c]) = make_uint2(l0, l1);
            if (t == TSTEPS - 1)
                *reinterpret_cast<float2*>(
                    g_h + (long long)(r0 + g) * HIDDENSZ + c) = make_float2(v0, v1);
            pcur[ni] = pn[ni];
        }
        __syncthreads();
        buf ^= 1;
    }
}

// ---------------------------------------------------------------------------
// Kernel 3: FC head via tf32 tensor cores. Tile 64b x 128v, smem 101KB ->
// 2 blocks/SM so fill overlaps mma. 8 warps = 2 m-groups(32b) x 4 n-groups(32v).
// ---------------------------------------------------------------------------
#define FCS 132

__global__ __launch_bounds__(256) void fc_kernel(const float* __restrict__ W_fc,
                                                 const float* __restrict__ b_fc,
                                                 float* __restrict__ out) {
    extern __shared__ unsigned sm_u[];
    unsigned* Ws = sm_u;               // [128][FCS] tf32 of W_fc tile
    unsigned* Hs = sm_u + 128 * FCS;   // [64][FCS]  tf32 of h tile

    const int tid  = threadIdx.x;
    const int lane = tid & 31;
    const int w    = tid >> 5;
    const int g    = lane >> 2;
    const int t4   = lane & 3;
    const int v0   = blockIdx.x * 128;
    const int b0   = blockIdx.y * 64;
    const int mw   = w >> 2;   // 0..1 (32 b-rows each)
    const int nw   = w & 3;    // 0..3 (32 v-cols each)

    for (int idx = tid; idx < 128 * 32; idx += 256) {
        int r = idx >> 5, c4 = idx & 31;
        float4 wv = reinterpret_cast<const float4*>(
            W_fc + (long long)(v0 + r) * HIDDENSZ)[c4];
        uint4 wt = {f2tf32(wv.x), f2tf32(wv.y), f2tf32(wv.z), f2tf32(wv.w)};
        *reinterpret_cast<uint4*>(Ws + r * FCS + c4 * 4) = wt;
    }
    for (int idx = tid; idx < 64 * 32; idx += 256) {
        int r = idx >> 5, c4 = idx & 31;
        float4 hv = reinterpret_cast<const float4*>(
            g_h + (long long)(b0 + r) * HIDDENSZ)[c4];
        uint4 ht = {f2tf32(hv.x), f2tf32(hv.y), f2tf32(hv.z), f2tf32(hv.w)};
        *reinterpret_cast<uint4*>(Hs + r * FCS + c4 * 4) = ht;
    }
    __syncthreads();

    float acc[2][4][4] = {};

    #pragma unroll
    for (int k = 0; k < 16; k++) {
        const int kc = k * 8 + t4;
        unsigned a[2][4], b[4][2];
        #pragma unroll
        for (int mi = 0; mi < 2; mi++) {
            const unsigned* base = Hs + (mw * 32 + mi * 16 + g) * FCS;
            a[mi][0] = base[kc];
            a[mi][1] = base[8 * FCS + kc];
            a[mi][2] = base[kc + 4];
            a[mi][3] = base[8 * FCS + kc + 4];
        }
        #pragma unroll
        for (int ni = 0; ni < 4; ni++) {
            const unsigned* base = Ws + (nw * 32 + ni * 8 + g) * FCS;
            b[ni][0] = base[kc];
            b[ni][1] = base[kc + 4];
        }
        #pragma unroll
        for (int mi = 0; mi < 2; mi++)
            #pragma unroll
            for (int ni = 0; ni < 4; ni++)
                mma_tf32(acc[mi][ni], a[mi], b[ni]);
    }

    #pragma unroll
    for (int ni = 0; ni < 4; ni++) {
        int v = v0 + nw * 32 + ni * 8 + 2 * t4;
        float2 bb = *reinterpret_cast<const float2*>(b_fc + v);
        #pragma unroll
        for (int mi = 0; mi < 2; mi++) {
            int br = b0 + mw * 32 + mi * 16 + g;
            float2 r0 = {acc[mi][ni][0] + bb.x, acc[mi][ni][1] + bb.y};
            float2 r1 = {acc[mi][ni][2] + bb.x, acc[mi][ni][3] + bb.y};
            *reinterpret_cast<float2*>(out + (long long)br * VOCABSZ + v) = r0;
            *reinterpret_cast<float2*>(out + (long long)(br + 8) * VOCABSZ + v) = r1;
        }
    }
}

// ---------------------------------------------------------------------------
// inputs (metadata order): x, emb, W_ih, W_hh, b_ih, b_hh, W_fc, b_fc
// ---------------------------------------------------------------------------
extern "C" void kernel_launch(void* const* d_in, const int* in_sizes, int n_in,
                              void* d_out, int out_size) {
    const void*  x    = d_in[0];
    const float* emb  = (const float*)d_in[1];
    const float* W_ih = (const float*)d_in[2];
    const float* W_hh = (const float*)d_in[3];
    const float* b_ih = (const float*)d_in[4];
    const float* b_hh = (const float*)d_in[5];
    const float* W_fc = (const float*)d_in[6];
    const float* b_fc = (const float*)d_in[7];
    float* out = (float*)d_out;

    probe_kernel<<<1, 32>>>(x);
    proj_kernel<<<VOCABSZ / 32, 128>>>(emb, W_ih, b_ih, b_hh);
    rnn_kernel<<<BATCHSZ / 8, 256>>>(x, W_hh);

    const int fc_smem = (128 + 64) * FCS * (int)sizeof(unsigned);  // 101376 B
    cudaFuncSetAttribute(fc_kernel, cudaFuncAttributeMaxDynamicSharedMemorySize,
                         fc_smem);
    dim3 fgrid(VOCABSZ / 128, BATCHSZ / 64);  // 250 x 16
    fc_kernel<<<fgrid, 256, fc_smem>>>(W_fc, b_fc, out);
}